// round 1
// baseline (speedup 1.0000x reference)
#include <cuda_runtime.h>
#include <cstdint>

#define CC 256
#define BB 1024
#define ROWS_PER_BLOCK 4
#define NPAIR (ROWS_PER_BLOCK / 2)

// Expanded symmetric edge-weight matrix: W[c*CC + j] = w3[e(min(c,j),max(c,j))], diag 0.
__device__ float g_W[CC * CC];

__global__ void build_W_kernel(const float* __restrict__ w3) {
    int idx = blockIdx.x * blockDim.x + threadIdx.x;
    if (idx >= CC * CC) return;
    int c = idx >> 8;
    int j = idx & 255;
    float v = 0.0f;
    if (c != j) {
        int p = c < j ? c : j;
        int q = c < j ? j : c;
        // np.triu_indices(CC, k=1) linearization
        int e = p * (2 * CC - p - 1) / 2 + (q - p - 1);
        v = w3[e];
    }
    g_W[idx] = v;
}

// ---- packed f32x2 helpers (sm_100a) ----
__device__ __forceinline__ unsigned long long pk2(float lo, float hi) {
    unsigned long long r;
    asm("mov.b64 %0, {%1, %2};" : "=l"(r) : "f"(lo), "f"(hi));
    return r;
}
__device__ __forceinline__ void upk2(unsigned long long v, float& lo, float& hi) {
    asm("mov.b64 {%0, %1}, %2;" : "=f"(lo), "=f"(hi) : "l"(v));
}
__device__ __forceinline__ unsigned long long add2(unsigned long long a, unsigned long long b) {
    unsigned long long r;
    asm("add.rn.f32x2 %0, %1, %2;" : "=l"(r) : "l"(a), "l"(b));
    return r;
}
__device__ __forceinline__ unsigned long long mul2(unsigned long long a, unsigned long long b) {
    unsigned long long r;
    asm("mul.rn.f32x2 %0, %1, %2;" : "=l"(r) : "l"(a), "l"(b));
    return r;
}
__device__ __forceinline__ unsigned long long fma2_(unsigned long long a, unsigned long long b, unsigned long long c) {
    unsigned long long r;
    asm("fma.rn.f32x2 %0, %1, %2, %3;" : "=l"(r) : "l"(a), "l"(b), "l"(c));
    return r;
}

// out[b,c] = sum_j u(|d|) * (x_j - x_c) * W[j,c],  d = x_c - x_j (sign folded into d)
// u(a) = 0.505*t + 0.495*|t|,  t = w2[0] + a*(w2[1] + a*(w2[2] + a*w2[3]))
__global__ __launch_bounds__(CC) void son_main_kernel(
    const float* __restrict__ x, const float* __restrict__ w1,
    const float* __restrict__ w2, float* __restrict__ out)
{
    __shared__ float2 xs[NPAIR][CC];  // xs[p][j] = (row 2p, row 2p+1) scaled by w1[j]

    const int tid = threadIdx.x;     // channel c
    const int r0 = blockIdx.x * ROWS_PER_BLOCK;

    const float w1j = w1[tid];
    float xr[ROWS_PER_BLOCK];
#pragma unroll
    for (int r = 0; r < ROWS_PER_BLOCK; r++)
        xr[r] = x[(r0 + r) * CC + tid] * w1j;
#pragma unroll
    for (int p = 0; p < NPAIR; p++)
        xs[p][tid] = make_float2(xr[2 * p], xr[2 * p + 1]);
    __syncthreads();

    const float c0 = w2[0], c1 = w2[1], c2 = w2[2], c3 = w2[3];
    const unsigned long long C0 = pk2(c0, c0), C1 = pk2(c1, c1);
    const unsigned long long C2 = pk2(c2, c2), C3 = pk2(c3, c3);
    const unsigned long long P5 = pk2(0.505f, 0.505f), P4 = pk2(0.495f, 0.495f);
    const unsigned long long AMASK = 0x7fffffff7fffffffULL;

    unsigned long long nxc[NPAIR], acc[NPAIR];
#pragma unroll
    for (int p = 0; p < NPAIR; p++) {
        nxc[p] = pk2(-xr[2 * p], -xr[2 * p + 1]);  // -x_c for the two rows of this pair
        acc[p] = 0ULL;                              // (0.0f, 0.0f)
    }

    const float* wp = g_W + tid;
#pragma unroll 8
    for (int j = 0; j < CC; j++) {
        float w = __ldg(wp + j * CC);               // coalesced, L2-resident
        unsigned long long w2p = pk2(w, w);
#pragma unroll
        for (int p = 0; p < NPAIR; p++) {
            unsigned long long xj = *reinterpret_cast<const unsigned long long*>(&xs[p][j]);  // LDS.64 broadcast
            unsigned long long d  = add2(xj, nxc[p]);        // d' = x_j - x_c (both rows)
            unsigned long long a  = d & AMASK;               // |d|
            unsigned long long t  = fma2_(C3, a, C2);
            t = fma2_(t, a, C1);
            t = fma2_(t, a, C0);
            unsigned long long u  = fma2_(P4, t & AMASK, mul2(P5, t));  // 0.505 t + 0.495 |t|
            acc[p] = fma2_(u, mul2(d, w2p), acc[p]);         // += u * d' * w
        }
    }

#pragma unroll
    for (int p = 0; p < NPAIR; p++) {
        float lo, hi;
        upk2(acc[p], lo, hi);
        out[(r0 + 2 * p) * CC + tid]     = lo;
        out[(r0 + 2 * p + 1) * CC + tid] = hi;
    }
}

extern "C" void kernel_launch(void* const* d_in, const int* in_sizes, int n_in,
                              void* d_out, int out_size) {
    // Identify inputs by element count (robust to ordering):
    // x: 262144, w1: 256, w2: 4, w3: 32640, diff_indices: 8355840 (unused)
    const float* x = nullptr;
    const float* w1 = nullptr;
    const float* w2 = nullptr;
    const float* w3 = nullptr;
    for (int i = 0; i < n_in; i++) {
        switch (in_sizes[i]) {
            case BB * CC:            x  = (const float*)d_in[i]; break;
            case CC:                 w1 = (const float*)d_in[i]; break;
            case 4:                  w2 = (const float*)d_in[i]; break;
            case CC * (CC - 1) / 2:  w3 = (const float*)d_in[i]; break;
            default: break;  // diff_indices not needed
        }
    }

    build_W_kernel<<<(CC * CC + 255) / 256, 256>>>(w3);
    son_main_kernel<<<BB / ROWS_PER_BLOCK, CC>>>(x, w1, w2, (float*)d_out);
}